// round 9
// baseline (speedup 1.0000x reference)
#include <cuda_runtime.h>
#include <math.h>

#define VV 100000
#define DD 128
#define BB 512
#define LL 20
#define TT 20
#define HH 32
#define CC 33
#define NN 10240           // BB*LL
#define RR 1056            // C*H
#define SCALE_F 12.0f
#define VTILES 782         // ceil(100000/128)

typedef unsigned long long ull;

// ---------------- scratch (static device allocations) ----------------------
__device__ float g_featn[NN * DD];
__device__ float g_embn[(size_t)VV * DD];
__device__ float g_X[BB * TT * CC];
__device__ float g_fv[BB * DD];
__device__ float g_e[NN];
__device__ float g_te[BB * DD];
__device__ float g_srT[DD * BB];          // transposed sr: [d][b]
__device__ float g_z[BB * HH];
__device__ float g_w2t[DD * RR];          // transposed cde_w2: [k][r]
__device__ float g_pmax[BB * VTILES];
__device__ float g_psum[BB * VTILES];
__device__ float g_lse[BB];

__device__ __forceinline__ float dot4(float4 a, float4 b) {
    return a.x * b.x + a.y * b.y + a.z * b.z + a.w * b.w;
}
__device__ __forceinline__ ull ffma2(ull a, ull b, ull c) {
    ull d;
    asm("fma.rn.f32x2 %0,%1,%2,%3;" : "=l"(d) : "l"(a), "l"(b), "l"(c));
    return d;
}
__device__ __forceinline__ ull addf32x2(ull a, ull b) {
    ull d;
    asm("add.rn.f32x2 %0,%1,%2;" : "=l"(d) : "l"(a), "l"(b));
    return d;
}
__device__ __forceinline__ ull dup2(float x) {
    ull d;
    asm("mov.b64 %0,{%1,%1};" : "=l"(d) : "f"(x));
    return d;
}
__device__ __forceinline__ float2 u2f(ull a) {
    float2 f;
    asm("mov.b64 {%0,%1},%2;" : "=f"(f.x), "=f"(f.y) : "l"(a));
    return f;
}
__device__ __forceinline__ float tanh_fast(float x) {
    float e = __expf(2.0f * x);
    return 1.0f - __fdividef(2.0f, e + 1.0f);
}
__device__ __forceinline__ void atomicMaxFloatShared(float* addr, float val) {
    int old = __float_as_int(*addr);
    while (__int_as_float(old) < val) {
        int assumed = old;
        old = atomicCAS((int*)addr, assumed, __float_as_int(val));
        if (old == assumed) break;
    }
}

// ---------------- fused normalization kernels (embn + featn + fode) ---------
__global__ void k_misc(const float* __restrict__ emb, const int* __restrict__ iid,
                       const int* __restrict__ eids, const float* __restrict__ red_w,
                       const float* __restrict__ red_b, const float* __restrict__ times) {
    int blk = blockIdx.x;
    int lane = threadIdx.x & 31;
    if (blk < 12500) {
        int row = blk * 8 + (threadIdx.x >> 5);
        if (row >= VV) return;
        const float4* s = (const float4*)(emb + (size_t)row * DD);
        float4 v = s[lane];
        float ss = v.x * v.x + v.y * v.y + v.z * v.z + v.w * v.w;
        #pragma unroll
        for (int o = 16; o; o >>= 1) ss += __shfl_xor_sync(0xffffffffu, ss, o);
        float inv = 1.0f / (sqrtf(ss) + 1e-12f);
        float4 r = make_float4(v.x * inv, v.y * inv, v.z * inv, v.w * inv);
        ((float4*)(g_embn + (size_t)row * DD))[lane] = r;
    } else if (blk < 12500 + 1280) {
        int row = (blk - 12500) * 8 + (threadIdx.x >> 5);
        if (row >= NN) return;
        const float4* s = (const float4*)(emb + (size_t)iid[row] * DD);
        float4 v = s[lane];
        float ss = v.x * v.x + v.y * v.y + v.z * v.z + v.w * v.w;
        #pragma unroll
        for (int o = 16; o; o >>= 1) ss += __shfl_xor_sync(0xffffffffu, ss, o);
        float inv = 1.0f / sqrtf(ss);
        float4 r = make_float4(v.x * inv, v.y * inv, v.z * inv, v.w * inv);
        ((float4*)(g_featn + (size_t)row * DD))[lane] = r;
    } else {
        int row = (blk - 13780) * 8 + (threadIdx.x >> 5);
        if (row >= BB * TT) return;
        const float4* s4 = (const float4*)(emb + (size_t)eids[row] * DD);
        const float4* w4 = (const float4*)(red_w + lane * DD);
        float acc = red_b[lane];
        #pragma unroll 8
        for (int k = 0; k < 32; k++) acc += dot4(s4[k], w4[k]);
        float ss = acc * acc;
        #pragma unroll
        for (int o = 16; o; o >>= 1) ss += __shfl_xor_sync(0xffffffffu, ss, o);
        float inv = 1.0f / (sqrtf(ss) + 1e-12f);
        float* Xr = g_X + row * CC;
        if (lane == 0) Xr[0] = times[row];
        Xr[1 + lane] = acc * inv;
    }
}

// ---------------- w2 transpose: g_w2t[k][r] = w2[r][k] -----------------------
__global__ void k_w2t(const float* __restrict__ w2) {
    int idx = blockIdx.x * 256 + threadIdx.x;
    if (idx >= RR * DD) return;
    int r = idx >> 7, k = idx & 127;
    g_w2t[k * RR + r] = w2[idx];
}

// ---------------- noop (aligns k_scan to the profiled launch slot) ----------
__global__ void k_noop() {}

// ---------------- fused RK4 scan: 64 independent CTAs, no inter-CTA sync ----
// CTA bt handles batches [bt*8, bt*8+8), full R=1056, all 19 RK4 steps.
__global__ void __launch_bounds__(256) k_scan(
        const float* __restrict__ w1, const float* __restrict__ b1,
        const float* __restrict__ b2,
        const float* __restrict__ init_w, const float* __restrict__ init_b) {
    __shared__ float s_w1[128 * 33];     // [j][h] pad 33
    __shared__ float s_b1[128];
    __shared__ float s_b2[RR];
    __shared__ float s_z[256];           // [b][h] b*32+h
    __shared__ float s_zevt[32 * 8];     // [h][b]
    __shared__ float s_h1t[128 * 8];     // [j][b]
    __shared__ float s_dx[8 * 34];       // [b][c] pad 34
    __shared__ float s_k[4][256];        // [sub][b*32+h]

    int tid = threadIdx.x;
    int b0 = blockIdx.x * 8;

    // ---- persistent loads ----
    for (int i = tid; i < 128 * 32; i += 256) {
        int j = i >> 5, h = i & 31;
        s_w1[j * 33 + h] = w1[i];
    }
    if (tid < 128) s_b1[tid] = b1[tid];
    for (int i = tid; i < RR; i += 256) s_b2[i] = b2[i];

    // ---- z0 = X[:,0] @ init_w.T + init_b  (one element per thread) ----
    {
        int b = tid >> 5, h = tid & 31;
        const float* x = g_X + (size_t)(b0 + b) * TT * CC;
        float acc = init_b[h];
        #pragma unroll
        for (int c = 0; c < CC; c++) acc += x[c] * init_w[h * CC + c];
        s_z[tid] = acc;
    }
    __syncthreads();

    int lane = tid & 31, w = tid >> 5;
    int j0 = tid >> 1;                 // h1 phase: j per thread pair
    int bh = (tid & 1) * 4;            // h1 phase: b-half
    int lr = 1024 + w * 4 + (lane >> 3);   // leftover row for this lane
    int kb2 = (lane & 7) * 16;             // leftover k-slice

    for (int s = 0; s < TT - 1; s++) {
        // dx for this step (FIX: strided loop covers all 8*CC = 264 elements)
        for (int i = tid; i < 8 * CC; i += 256) {
            int b = i / CC, c = i - b * CC;
            int base = (b0 + b) * TT * CC + s * CC + c;
            s_dx[b * 34 + c] = g_X[base + CC] - g_X[base];
        }
        // z += (k1 + 2k2 + 2k3 + k4)/6 from previous step
        if (s > 0) {
            float c1 = s_k[0][tid], c2 = s_k[1][tid], c3 = s_k[2][tid], c4 = s_k[3][tid];
            s_z[tid] += (c1 + 2.0f * (c2 + c3) + c4) * (1.0f / 6.0f);
        }

        for (int sub = 0; sub < 4; sub++) {
            // ---- build z_eval (transposed) + zero s_k[sub] ----
            {
                int b = tid >> 5, h = tid & 31;
                float zv = s_z[tid];
                if (sub == 1) zv += 0.5f * s_k[0][tid];
                else if (sub == 2) zv += 0.5f * s_k[1][tid];
                else if (sub == 3) zv += s_k[2][tid];
                s_zevt[h * 8 + b] = zv;
                s_k[sub][tid] = 0.0f;
            }
            __syncthreads();

            // ---- h1 = relu(zev @ w1.T + b1), stored [j][b] ----
            {
                ull a0 = 0ULL, a1 = 0ULL;
                #pragma unroll 8
                for (int h = 0; h < 32; h++) {
                    ull wd = dup2(s_w1[j0 * 33 + h]);
                    ull z0 = *(const ull*)&s_zevt[h * 8 + bh];
                    ull z1 = *(const ull*)&s_zevt[h * 8 + bh + 2];
                    a0 = ffma2(z0, wd, a0);
                    a1 = ffma2(z1, wd, a1);
                }
                float bj = s_b1[j0];
                float2 f0 = u2f(a0), f1 = u2f(a1);
                s_h1t[j0 * 8 + bh + 0] = fmaxf(f0.x + bj, 0.0f);
                s_h1t[j0 * 8 + bh + 1] = fmaxf(f0.y + bj, 0.0f);
                s_h1t[j0 * 8 + bh + 2] = fmaxf(f1.x + bj, 0.0f);
                s_h1t[j0 * 8 + bh + 3] = fmaxf(f1.y + bj, 0.0f);
            }
            __syncthreads();

            // ---- main GEMM: rows 4*tid..4*tid+3, 8 b, k=0..127 ----
            ull acc[4][4];
            #pragma unroll
            for (int r = 0; r < 4; r++)
                #pragma unroll
                for (int p = 0; p < 4; p++) acc[r][p] = 0ULL;

            {
                const float4* wp = (const float4*)(g_w2t) + tid;   // row group 4*tid at k=0
                #pragma unroll 4
                for (int k = 0; k < 128; k++) {
                    float4 wv = wp[k * (RR / 4)];
                    float4 h01 = *(const float4*)&s_h1t[k * 8];
                    float4 h23 = *(const float4*)&s_h1t[k * 8 + 4];
                    ull hp[4];
                    hp[0] = ((const ull*)&h01)[0]; hp[1] = ((const ull*)&h01)[1];
                    hp[2] = ((const ull*)&h23)[0]; hp[3] = ((const ull*)&h23)[1];
                    float wr[4] = {wv.x, wv.y, wv.z, wv.w};
                    #pragma unroll
                    for (int r = 0; r < 4; r++) {
                        ull cd = dup2(wr[r]);
                        #pragma unroll
                        for (int p = 0; p < 4; p++) acc[r][p] = ffma2(hp[p], cd, acc[r][p]);
                    }
                }
            }

            // ---- leftover rows 1024..1055: k-split over lane octets ----
            ull lacc[4];
            #pragma unroll
            for (int p = 0; p < 4; p++) lacc[p] = 0ULL;
            {
                const float* wc = g_w2t + lr;
                #pragma unroll 4
                for (int kk = 0; kk < 16; kk++) {
                    int k = kb2 + kk;
                    ull cd = dup2(wc[k * RR]);
                    float4 h01 = *(const float4*)&s_h1t[k * 8];
                    float4 h23 = *(const float4*)&s_h1t[k * 8 + 4];
                    lacc[0] = ffma2(((const ull*)&h01)[0], cd, lacc[0]);
                    lacc[1] = ffma2(((const ull*)&h01)[1], cd, lacc[1]);
                    lacc[2] = ffma2(((const ull*)&h23)[0], cd, lacc[2]);
                    lacc[3] = ffma2(((const ull*)&h23)[1], cd, lacc[3]);
                }
                #pragma unroll
                for (int off = 1; off <= 4; off <<= 1)
                    #pragma unroll
                    for (int p = 0; p < 4; p++)
                        lacc[p] = addf32x2(lacc[p], __shfl_xor_sync(0xffffffffu, lacc[p], off));
            }

            // ---- epilogue: tanh + contract with dx, accumulate into s_k[sub] ----
            {
                int r0g = 4 * tid;
                int h0 = r0g / 33;
                float a0r[8], a1r[8];
                #pragma unroll
                for (int b = 0; b < 8; b++) { a0r[b] = 0.0f; a1r[b] = 0.0f; }
                #pragma unroll
                for (int r = 0; r < 4; r++) {
                    int rg = r0g + r;
                    int h = rg / 33;
                    int c = rg - 33 * h;
                    float bias = s_b2[rg];
                    int sl = h - h0;
                    #pragma unroll
                    for (int p = 0; p < 4; p++) {
                        float2 f = u2f(acc[r][p]);
                        float t0 = tanh_fast(f.x + bias);
                        float t1 = tanh_fast(f.y + bias);
                        float g0 = t0 * s_dx[(2 * p) * 34 + c];
                        float g1 = t1 * s_dx[(2 * p + 1) * 34 + c];
                        if (sl == 0) { a0r[2 * p] += g0; a0r[2 * p + 1] += g1; }
                        else         { a1r[2 * p] += g0; a1r[2 * p + 1] += g1; }
                    }
                }
                #pragma unroll
                for (int b = 0; b < 8; b++) {
                    atomicAdd(&s_k[sub][b * 32 + h0], a0r[b]);
                    atomicAdd(&s_k[sub][b * 32 + h0 + 1], a1r[b]);
                }
                // leftover epilogue (one lane per row): rows 1024.. have h=31
                if ((lane & 7) == 0) {
                    int c = lr - 1023;
                    float bias = s_b2[lr];
                    #pragma unroll
                    for (int p = 0; p < 4; p++) {
                        float2 f = u2f(lacc[p]);
                        float t0 = tanh_fast(f.x + bias);
                        float t1 = tanh_fast(f.y + bias);
                        atomicAdd(&s_k[sub][(2 * p) * 32 + 31],     t0 * s_dx[(2 * p) * 34 + c]);
                        atomicAdd(&s_k[sub][(2 * p + 1) * 32 + 31], t1 * s_dx[(2 * p + 1) * 34 + c]);
                    }
                }
            }
            __syncthreads();
        }
    }

    // ---- final z write ----
    {
        float c1 = s_k[0][tid], c2 = s_k[1][tid], c3 = s_k[2][tid], c4 = s_k[3][tid];
        float zf = s_z[tid] + (c1 + 2.0f * (c2 + c3) + c4) * (1.0f / 6.0f);
        int b = tid >> 5, h = tid & 31;
        g_z[(b0 + b) * HH + h] = zf;
    }
}

// ---------------- fused te + fv ----------------------------------------------
__global__ void k_tefv(const float* __restrict__ rec_w, const float* __restrict__ rec_b,
                       const float* __restrict__ fcv_w, const float* __restrict__ fcv_b,
                       const int* __restrict__ last_nodes) {
    int b = blockIdx.x, t = threadIdx.x;
    __shared__ float zs[HH];
    __shared__ float fs[DD];
    if (t < HH) zs[t] = g_z[b * HH + t];
    if (t >= 128) fs[t - 128] = g_featn[(size_t)last_nodes[b] * DD + (t - 128)];
    __syncthreads();
    if (t < 128) {
        float acc = rec_b[t];
        #pragma unroll
        for (int h = 0; h < HH; h++) acc += zs[h] * rec_w[t * HH + h];
        g_te[b * DD + t] = acc;
    } else {
        int d = t - 128;
        const float4* w4 = (const float4*)(fcv_w + d * DD);
        const float4* f4 = (const float4*)fs;
        float acc = fcv_b[d];
        #pragma unroll 8
        for (int k = 0; k < 32; k++) acc += dot4(f4[k], w4[k]);
        g_fv[b * DD + d] = acc;
    }
}

// ---------------- e[n] = sigmoid(featn@fcu.T + fv[seg]) . fce ----------------
__global__ void k_e(const float* __restrict__ fcu_w, const float* __restrict__ fce_w,
                    const int* __restrict__ seg_ids) {
    int n0 = blockIdx.x * 16;
    int d = threadIdx.x;
    __shared__ float fs[16][128];
    __shared__ float es[16];
    for (int i = d; i < 16 * 128; i += 128) ((float*)fs)[i] = g_featn[(size_t)n0 * DD + i];
    if (d < 16) es[d] = 0.0f;
    __syncthreads();
    float acc[16];
    #pragma unroll
    for (int n = 0; n < 16; n++) acc[n] = 0.0f;
    const float4* w4 = (const float4*)(fcu_w + d * DD);
    for (int k4 = 0; k4 < 32; k4++) {
        float4 wv = w4[k4];
        #pragma unroll
        for (int n = 0; n < 16; n++) {
            float4 a = *(const float4*)(&fs[n][k4 * 4]);
            acc[n] += dot4(a, wv);
        }
    }
    float fcw = fce_w[d];
    #pragma unroll
    for (int n = 0; n < 16; n++) {
        int seg = seg_ids[n0 + n];
        float s = fcw / (1.0f + expf(-(acc[n] + g_fv[seg * DD + d])));
        #pragma unroll
        for (int o = 16; o; o >>= 1) s += __shfl_xor_sync(0xffffffffu, s, o);
        if ((d & 31) == 0) atomicAdd(&es[n], s);
    }
    __syncthreads();
    if (d < 16) g_e[n0 + d] = es[d];
}

// ---------------- segment softmax + sr (writes transposed srT) ---------------
__global__ void k_seg(const float* __restrict__ fcsr_w, const int* __restrict__ last_nodes) {
    int b = blockIdx.x, d = threadIdx.x;
    __shared__ float al[LL];
    __shared__ float srl[DD], srg[DD];
    __shared__ float red[4];
    if (d == 0) {
        float m = -1e30f;
        for (int n = 0; n < LL; n++) m = fmaxf(m, g_e[b * LL + n]);
        float s = 0.0f;
        for (int n = 0; n < LL; n++) { float ee = expf(g_e[b * LL + n] - m); al[n] = ee; s += ee; }
        float inv = 1.0f / s;
        for (int n = 0; n < LL; n++) al[n] *= inv;
    }
    __syncthreads();
    float sg = 0.0f;
    for (int n = 0; n < LL; n++) sg += al[n] * g_featn[(size_t)(b * LL + n) * DD + d];
    float sl = g_featn[(size_t)last_nodes[b] * DD + d];
    srl[d] = sl; srg[d] = sg;
    __syncthreads();
    float acc = g_te[b * DD + d];
    const float4* w4 = (const float4*)(fcsr_w + d * 2 * DD);
    const float4* l4 = (const float4*)srl;
    const float4* g4 = (const float4*)srg;
    #pragma unroll 8
    for (int k = 0; k < 32; k++) acc += dot4(l4[k], w4[k]);
    #pragma unroll 8
    for (int k = 0; k < 32; k++) acc += dot4(g4[k], w4[32 + k]);
    float ss = acc * acc;
    #pragma unroll
    for (int o = 16; o; o >>= 1) ss += __shfl_xor_sync(0xffffffffu, ss, o);
    if ((d & 31) == 0) red[d >> 5] = ss;
    __syncthreads();
    float tot = red[0] + red[1] + red[2] + red[3];
    float inv = 1.0f / (sqrtf(tot) + 1e-12f);
    g_srT[d * BB + b] = acc * inv;
}

// ---------------- logits GEMM (f32x2, srT, max-based softmax) -----------------
// grid (4 b-tiles, 782 v-tiles), 256 threads, tile 128b x 128v
#define LOG_SMEM_FLOATS (128*128 + 128*128 + 128 + 128)
__global__ void __launch_bounds__(256) k_logits(float* __restrict__ out) {
    extern __shared__ float sm[];
    float* sA = sm;                  // [k=128][b=128]
    float* sB = sA + 128 * 128;      // [v=128][k=128]
    float* sM = sB + 128 * 128;      // 128
    float* sS = sM + 128;            // 128
    int bt = blockIdx.x, vt = blockIdx.y;
    int b0c = bt * 128, v0c = vt * 128;
    int tid = threadIdx.x;
    bool full = (v0c + 128 <= VV);

    #pragma unroll
    for (int j = 0; j < 16; j++) {
        int idx4 = tid + j * 256;
        int k = idx4 >> 5, q = idx4 & 31;
        ((float4*)(sA + k * 128))[q] = ((const float4*)(g_srT + (size_t)k * BB + b0c))[q];
    }
    #pragma unroll
    for (int j = 0; j < 16; j++) {
        int idx4 = tid + j * 256;
        int v = idx4 >> 5, k4 = idx4 & 31;
        int vg = v0c + v;
        float4 val = make_float4(0.f, 0.f, 0.f, 0.f);
        if (vg < VV) val = ((const float4*)(g_embn + (size_t)vg * DD))[k4];
        ((float4*)(sB + v * 128))[k4] = val;
    }
    if (tid < 128) { sM[tid] = -1e30f; sS[tid] = 0.0f; }
    __syncthreads();

    int w = tid >> 5, lane = tid & 31;
    int bq = lane & 15, vh = lane >> 4;
    int v0l = w * 16 + vh * 8;

    ull acc[4][8];
    #pragma unroll
    for (int p = 0; p < 4; p++)
        #pragma unroll
        for (int j = 0; j < 8; j++) acc[p][j] = 0ULL;

    #pragma unroll 1
    for (int k4 = 0; k4 < 32; k4++) {
        int k = k4 * 4;
        float4 bv[8];
        #pragma unroll
        for (int j = 0; j < 8; j++) bv[j] = *(const float4*)&sB[(v0l + j) * 128 + k];
        #pragma unroll
        for (int i = 0; i < 4; i++) {
            ull a[4];
            #pragma unroll
            for (int p = 0; p < 4; p++) a[p] = *(const ull*)&sA[(k + i) * 128 + 2 * bq + 32 * p];
            #pragma unroll
            for (int j = 0; j < 8; j++) {
                float c = (i == 0) ? bv[j].x : (i == 1) ? bv[j].y : (i == 2) ? bv[j].z : bv[j].w;
                ull bd = dup2(c);
                #pragma unroll
                for (int p = 0; p < 4; p++) acc[p][j] = ffma2(a[p], bd, acc[p][j]);
            }
        }
    }

    // phase 1: per-b tile max
    #pragma unroll
    for (int p = 0; p < 4; p++) {
        int be = 2 * bq + 32 * p;
        float me = -1e30f, mo = -1e30f;
        #pragma unroll
        for (int j = 0; j < 8; j++) {
            if (full || (v0c + v0l + j < VV)) {
                float2 f = u2f(acc[p][j]);
                me = fmaxf(me, SCALE_F * f.x);
                mo = fmaxf(mo, SCALE_F * f.y);
            }
        }
        atomicMaxFloatShared(&sM[be], me);
        atomicMaxFloatShared(&sM[be + 1], mo);
    }
    __syncthreads();

    // phase 2: exp-sums + store logits
    #pragma unroll
    for (int p = 0; p < 4; p++) {
        int be = 2 * bq + 32 * p, bo = be + 1;
        float m0 = sM[be], m1 = sM[bo];
        float s0 = 0.0f, s1 = 0.0f;
        float r0a[8], r1a[8];
        #pragma unroll
        for (int j = 0; j < 8; j++) {
            float2 f = u2f(acc[p][j]);
            float x = SCALE_F * f.x, y = SCALE_F * f.y;
            r0a[j] = x; r1a[j] = y;
            if (full || (v0c + v0l + j < VV)) {
                s0 += __expf(x - m0);
                s1 += __expf(y - m1);
            }
        }
        size_t base0 = (size_t)(b0c + be) * VV + v0c + v0l;
        size_t base1 = (size_t)(b0c + bo) * VV + v0c + v0l;
        if (full) {
            ((float4*)(out + base0))[0] = make_float4(r0a[0], r0a[1], r0a[2], r0a[3]);
            ((float4*)(out + base0))[1] = make_float4(r0a[4], r0a[5], r0a[6], r0a[7]);
            ((float4*)(out + base1))[0] = make_float4(r1a[0], r1a[1], r1a[2], r1a[3]);
            ((float4*)(out + base1))[1] = make_float4(r1a[4], r1a[5], r1a[6], r1a[7]);
        } else {
            #pragma unroll
            for (int j = 0; j < 8; j++) {
                if (v0c + v0l + j < VV) {
                    out[base0 + j] = r0a[j];
                    out[base1 + j] = r1a[j];
                }
            }
        }
        atomicAdd(&sS[be], s0);
        atomicAdd(&sS[bo], s1);
    }
    __syncthreads();
    if (tid < 128) {
        g_pmax[(size_t)(b0c + tid) * VTILES + vt] = sM[tid];
        g_psum[(size_t)(b0c + tid) * VTILES + vt] = sS[tid];
    }
}

// ---------------- lse reduce (max-based) --------------------------------------
__global__ void k_lse() {
    int b = blockIdx.x, tid = threadIdx.x;
    __shared__ float red[256];
    float m = -1e30f;
    for (int t = tid; t < VTILES; t += 256) m = fmaxf(m, g_pmax[(size_t)b * VTILES + t]);
    red[tid] = m;
    __syncthreads();
    for (int o = 128; o; o >>= 1) { if (tid < o) red[tid] = fmaxf(red[tid], red[tid + o]); __syncthreads(); }
    float M = red[0];
    __syncthreads();
    float s = 0.0f;
    for (int t = tid; t < VTILES; t += 256)
        s += g_psum[(size_t)b * VTILES + t] * expf(g_pmax[(size_t)b * VTILES + t] - M);
    red[tid] = s;
    __syncthreads();
    for (int o = 128; o; o >>= 1) { if (tid < o) red[tid] += red[tid + o]; __syncthreads(); }
    if (tid == 0) g_lse[b] = M + logf(red[0]);
}

// ---------------- final fix: out -= lse[b] (2D grid, no div) ------------------
__global__ void k_fix(float* __restrict__ out) {
    int b = blockIdx.y;
    int i4 = blockIdx.x * 256 + threadIdx.x;
    if (i4 >= VV / 4) return;
    float l = g_lse[b];
    float4* o4 = (float4*)(out + (size_t)b * VV);
    float4 v = o4[i4];
    v.x -= l; v.y -= l; v.z -= l; v.w -= l;
    o4[i4] = v;
}

// =============================================================================
extern "C" void kernel_launch(void* const* d_in, const int* in_sizes, int n_in,
                              void* d_out, int out_size) {
    const float* emb      = (const float*)d_in[0];
    const float* fcu_w    = (const float*)d_in[7];
    const float* fcv_w    = (const float*)d_in[8];
    const float* fcv_b    = (const float*)d_in[9];
    const float* fce_w    = (const float*)d_in[10];
    const float* fcsr_w   = (const float*)d_in[11];
    const float* red_w    = (const float*)d_in[12];
    const float* red_b    = (const float*)d_in[13];
    const float* rec_w    = (const float*)d_in[14];
    const float* rec_b    = (const float*)d_in[15];
    const float* cde_w1   = (const float*)d_in[16];
    const float* cde_b1   = (const float*)d_in[17];
    const float* cde_w2   = (const float*)d_in[18];
    const float* cde_b2   = (const float*)d_in[19];
    const float* init_w   = (const float*)d_in[20];
    const float* init_b   = (const float*)d_in[21];
    const float* times    = (const float*)d_in[23];
    const int*   iid      = (const int*)d_in[24];
    const int*   seg_ids  = (const int*)d_in[27];
    const int*   last_nd  = (const int*)d_in[28];
    const int*   eids     = (const int*)d_in[29];
    float* out = (float*)d_out;

    const int log_smem = LOG_SMEM_FLOATS * 4;
    cudaFuncSetAttribute(k_logits, cudaFuncAttributeMaxDynamicSharedMemorySize, log_smem);

    k_misc<<<15060, 256>>>(emb, iid, eids, red_w, red_b, times);    // launch 1
    k_w2t<<<(RR * DD + 255) / 256, 256>>>(cde_w2);                   // launch 2
    k_noop<<<1, 32>>>();                                             // launch 3
    k_scan<<<64, 256>>>(cde_w1, cde_b1, cde_b2, init_w, init_b);     // launch 4 (profiled)
    k_tefv<<<BB, 256>>>(rec_w, rec_b, fcv_w, fcv_b, last_nd);
    k_e<<<NN / 16, 128>>>(fcu_w, fce_w, seg_ids);
    k_seg<<<BB, 128>>>(fcsr_w, last_nd);
    k_logits<<<dim3(4, VTILES), 256, log_smem>>>(out);
    k_lse<<<BB, 256>>>();
    k_fix<<<dim3((VV / 4 + 255) / 256, BB), 256>>>(out);
}

// round 10
// speedup vs baseline: 1.1270x; 1.1270x over previous
#include <cuda_runtime.h>
#include <math.h>

#define VV 100000
#define DD 128
#define BB 512
#define LL 20
#define TT 20
#define HH 32
#define CC 33
#define NN 10240           // BB*LL
#define RR 1056            // C*H
#define SCALE_F 12.0f
#define VTILES 782         // ceil(100000/128)

typedef unsigned long long ull;

// ---------------- scratch (static device allocations) ----------------------
__device__ float g_featn[NN * DD];
__device__ float g_embn[(size_t)VV * DD];
__device__ float g_X[BB * TT * CC];
__device__ float g_fv[BB * DD];
__device__ float g_e[NN];
__device__ float g_te[BB * DD];
__device__ float g_srT[DD * BB];          // transposed sr: [d][b]
__device__ float g_z[BB * HH];
__device__ float g_w2t[DD * RR];          // transposed cde_w2: [k][r]
__device__ float g_pmax[BB * VTILES];
__device__ float g_psum[BB * VTILES];
__device__ float g_lse[BB];

__device__ __forceinline__ float dot4(float4 a, float4 b) {
    return a.x * b.x + a.y * b.y + a.z * b.z + a.w * b.w;
}
__device__ __forceinline__ ull ffma2(ull a, ull b, ull c) {
    ull d;
    asm("fma.rn.f32x2 %0,%1,%2,%3;" : "=l"(d) : "l"(a), "l"(b), "l"(c));
    return d;
}
__device__ __forceinline__ ull addf32x2(ull a, ull b) {
    ull d;
    asm("add.rn.f32x2 %0,%1,%2;" : "=l"(d) : "l"(a), "l"(b));
    return d;
}
__device__ __forceinline__ ull dup2(float x) {
    ull d;
    asm("mov.b64 %0,{%1,%1};" : "=l"(d) : "f"(x));
    return d;
}
__device__ __forceinline__ float2 u2f(ull a) {
    float2 f;
    asm("mov.b64 {%0,%1},%2;" : "=f"(f.x), "=f"(f.y) : "l"(a));
    return f;
}
__device__ __forceinline__ float tanh_fast(float x) {
    float e = __expf(2.0f * x);
    return 1.0f - __fdividef(2.0f, e + 1.0f);
}
__device__ __forceinline__ void atomicMaxFloatShared(float* addr, float val) {
    int old = __float_as_int(*addr);
    while (__int_as_float(old) < val) {
        int assumed = old;
        old = atomicCAS((int*)addr, assumed, __float_as_int(val));
        if (old == assumed) break;
    }
}

// ---------------- fused normalization kernels (embn + featn + fode) ---------
__global__ void k_misc(const float* __restrict__ emb, const int* __restrict__ iid,
                       const int* __restrict__ eids, const float* __restrict__ red_w,
                       const float* __restrict__ red_b, const float* __restrict__ times) {
    int blk = blockIdx.x;
    int lane = threadIdx.x & 31;
    if (blk < 12500) {
        int row = blk * 8 + (threadIdx.x >> 5);
        if (row >= VV) return;
        const float4* s = (const float4*)(emb + (size_t)row * DD);
        float4 v = s[lane];
        float ss = v.x * v.x + v.y * v.y + v.z * v.z + v.w * v.w;
        #pragma unroll
        for (int o = 16; o; o >>= 1) ss += __shfl_xor_sync(0xffffffffu, ss, o);
        float inv = 1.0f / (sqrtf(ss) + 1e-12f);
        float4 r = make_float4(v.x * inv, v.y * inv, v.z * inv, v.w * inv);
        ((float4*)(g_embn + (size_t)row * DD))[lane] = r;
    } else if (blk < 12500 + 1280) {
        int row = (blk - 12500) * 8 + (threadIdx.x >> 5);
        if (row >= NN) return;
        const float4* s = (const float4*)(emb + (size_t)iid[row] * DD);
        float4 v = s[lane];
        float ss = v.x * v.x + v.y * v.y + v.z * v.z + v.w * v.w;
        #pragma unroll
        for (int o = 16; o; o >>= 1) ss += __shfl_xor_sync(0xffffffffu, ss, o);
        float inv = 1.0f / sqrtf(ss);
        float4 r = make_float4(v.x * inv, v.y * inv, v.z * inv, v.w * inv);
        ((float4*)(g_featn + (size_t)row * DD))[lane] = r;
    } else {
        int row = (blk - 13780) * 8 + (threadIdx.x >> 5);
        if (row >= BB * TT) return;
        const float4* s4 = (const float4*)(emb + (size_t)eids[row] * DD);
        const float4* w4 = (const float4*)(red_w + lane * DD);
        float acc = red_b[lane];
        #pragma unroll 8
        for (int k = 0; k < 32; k++) acc += dot4(s4[k], w4[k]);
        float ss = acc * acc;
        #pragma unroll
        for (int o = 16; o; o >>= 1) ss += __shfl_xor_sync(0xffffffffu, ss, o);
        float inv = 1.0f / (sqrtf(ss) + 1e-12f);
        float* Xr = g_X + row * CC;
        if (lane == 0) Xr[0] = times[row];
        Xr[1 + lane] = acc * inv;
    }
}

// ---------------- w2 transpose: g_w2t[k][r] = w2[r][k] -----------------------
__global__ void k_w2t(const float* __restrict__ w2) {
    int idx = blockIdx.x * 256 + threadIdx.x;
    if (idx >= RR * DD) return;
    int r = idx >> 7, k = idx & 127;
    g_w2t[k * RR + r] = w2[idx];
}

// ---------------- noop (aligns k_scan to the profiled launch slot) ----------
__global__ void k_noop() {}

// ---------------- fused RK4 scan: 64 independent CTAs, no inter-CTA sync ----
// CTA bt handles batches [bt*8, bt*8+8), full R=1056, all 19 RK4 steps.
// w2t streamed from L2 with explicit 8-deep register prefetch (MLP=8).
__global__ void __launch_bounds__(256) k_scan(
        const float* __restrict__ w1, const float* __restrict__ b1,
        const float* __restrict__ b2,
        const float* __restrict__ init_w, const float* __restrict__ init_b) {
    __shared__ float s_w1[128 * 33];     // [j][h] pad 33
    __shared__ float s_b1[128];
    __shared__ float s_b2[RR];
    __shared__ float s_z[256];           // [b][h] b*32+h
    __shared__ float s_zevt[32 * 8];     // [h][b]
    __shared__ float s_h1t[128 * 8];     // [j][b]
    __shared__ float s_dx[8 * 34];       // [b][c] pad 34
    __shared__ float s_k[4][256];        // [sub][b*32+h]

    int tid = threadIdx.x;
    int b0 = blockIdx.x * 8;

    // ---- persistent loads ----
    for (int i = tid; i < 128 * 32; i += 256) {
        int j = i >> 5, h = i & 31;
        s_w1[j * 33 + h] = w1[i];
    }
    if (tid < 128) s_b1[tid] = b1[tid];
    for (int i = tid; i < RR; i += 256) s_b2[i] = b2[i];

    // ---- z0 = X[:,0] @ init_w.T + init_b  (one element per thread) ----
    {
        int b = tid >> 5, h = tid & 31;
        const float* x = g_X + (size_t)(b0 + b) * TT * CC;
        float acc = init_b[h];
        #pragma unroll
        for (int c = 0; c < CC; c++) acc += x[c] * init_w[h * CC + c];
        s_z[tid] = acc;
    }
    __syncthreads();

    int lane = tid & 31, w = tid >> 5;
    int j0 = tid >> 1;                 // h1 phase: j per thread pair
    int bh = (tid & 1) * 4;            // h1 phase: b-half
    int lr = 1024 + w * 4 + (lane >> 3);   // leftover row for this lane
    int kb2 = (lane & 7) * 16;             // leftover k-slice

    for (int s = 0; s < TT - 1; s++) {
        // dx for this step (strided loop covers all 8*CC = 264 elements)
        for (int i = tid; i < 8 * CC; i += 256) {
            int b = i / CC, c = i - b * CC;
            int base = (b0 + b) * TT * CC + s * CC + c;
            s_dx[b * 34 + c] = g_X[base + CC] - g_X[base];
        }
        // z += (k1 + 2k2 + 2k3 + k4)/6 from previous step
        if (s > 0) {
            float c1 = s_k[0][tid], c2 = s_k[1][tid], c3 = s_k[2][tid], c4 = s_k[3][tid];
            s_z[tid] += (c1 + 2.0f * (c2 + c3) + c4) * (1.0f / 6.0f);
        }

        for (int sub = 0; sub < 4; sub++) {
            // ---- build z_eval (transposed) + zero s_k[sub] ----
            {
                int b = tid >> 5, h = tid & 31;
                float zv = s_z[tid];
                if (sub == 1) zv += 0.5f * s_k[0][tid];
                else if (sub == 2) zv += 0.5f * s_k[1][tid];
                else if (sub == 3) zv += s_k[2][tid];
                s_zevt[h * 8 + b] = zv;
                s_k[sub][tid] = 0.0f;
            }
            __syncthreads();

            // ---- h1 = relu(zev @ w1.T + b1), stored [j][b] ----
            {
                ull a0 = 0ULL, a1 = 0ULL;
                #pragma unroll 8
                for (int h = 0; h < 32; h++) {
                    ull wd = dup2(s_w1[j0 * 33 + h]);
                    ull z0 = *(const ull*)&s_zevt[h * 8 + bh];
                    ull z1 = *(const ull*)&s_zevt[h * 8 + bh + 2];
                    a0 = ffma2(z0, wd, a0);
                    a1 = ffma2(z1, wd, a1);
                }
                float bj = s_b1[j0];
                float2 f0 = u2f(a0), f1 = u2f(a1);
                s_h1t[j0 * 8 + bh + 0] = fmaxf(f0.x + bj, 0.0f);
                s_h1t[j0 * 8 + bh + 1] = fmaxf(f0.y + bj, 0.0f);
                s_h1t[j0 * 8 + bh + 2] = fmaxf(f1.x + bj, 0.0f);
                s_h1t[j0 * 8 + bh + 3] = fmaxf(f1.y + bj, 0.0f);
            }
            __syncthreads();

            // ---- main GEMM: rows 4*tid..4*tid+3, 8 b, k=0..127 ----
            // explicit 8-deep register prefetch pipeline on w2t loads
            ull acc[4][4];
            #pragma unroll
            for (int r = 0; r < 4; r++)
                #pragma unroll
                for (int p = 0; p < 4; p++) acc[r][p] = 0ULL;

            {
                const float4* wp = (const float4*)(g_w2t) + tid;   // row group 4*tid at k=0
                float4 wv[8];
                #pragma unroll
                for (int i = 0; i < 8; i++) wv[i] = wp[i * (RR / 4)];

                #pragma unroll 1
                for (int kb = 0; kb < 128; kb += 8) {
                    bool more = (kb + 8) < 128;
                    #pragma unroll
                    for (int i = 0; i < 8; i++) {
                        int k = kb + i;
                        float4 cur = wv[i];
                        if (more) wv[i] = wp[(k + 8) * (RR / 4)];
                        float4 h01 = *(const float4*)&s_h1t[k * 8];
                        float4 h23 = *(const float4*)&s_h1t[k * 8 + 4];
                        ull hp0 = ((const ull*)&h01)[0], hp1 = ((const ull*)&h01)[1];
                        ull hp2 = ((const ull*)&h23)[0], hp3 = ((const ull*)&h23)[1];
                        float wr[4] = {cur.x, cur.y, cur.z, cur.w};
                        #pragma unroll
                        for (int r = 0; r < 4; r++) {
                            ull cd = dup2(wr[r]);
                            acc[r][0] = ffma2(hp0, cd, acc[r][0]);
                            acc[r][1] = ffma2(hp1, cd, acc[r][1]);
                            acc[r][2] = ffma2(hp2, cd, acc[r][2]);
                            acc[r][3] = ffma2(hp3, cd, acc[r][3]);
                        }
                    }
                }
            }

            // ---- leftover rows 1024..1055: k-split over lane octets ----
            // batch all 16 scalar loads up-front (MLP=16)
            ull lacc[4];
            #pragma unroll
            for (int p = 0; p < 4; p++) lacc[p] = 0ULL;
            {
                const float* wc = g_w2t + lr;
                float wl[16];
                #pragma unroll
                for (int kk = 0; kk < 16; kk++) wl[kk] = wc[(kb2 + kk) * RR];
                #pragma unroll
                for (int kk = 0; kk < 16; kk++) {
                    int k = kb2 + kk;
                    ull cd = dup2(wl[kk]);
                    float4 h01 = *(const float4*)&s_h1t[k * 8];
                    float4 h23 = *(const float4*)&s_h1t[k * 8 + 4];
                    lacc[0] = ffma2(((const ull*)&h01)[0], cd, lacc[0]);
                    lacc[1] = ffma2(((const ull*)&h01)[1], cd, lacc[1]);
                    lacc[2] = ffma2(((const ull*)&h23)[0], cd, lacc[2]);
                    lacc[3] = ffma2(((const ull*)&h23)[1], cd, lacc[3]);
                }
                #pragma unroll
                for (int off = 1; off <= 4; off <<= 1)
                    #pragma unroll
                    for (int p = 0; p < 4; p++)
                        lacc[p] = addf32x2(lacc[p], __shfl_xor_sync(0xffffffffu, lacc[p], off));
            }

            // ---- epilogue: tanh + contract with dx, accumulate into s_k[sub] ----
            {
                int r0g = 4 * tid;
                int h0 = r0g / 33;
                float a0r[8], a1r[8];
                #pragma unroll
                for (int b = 0; b < 8; b++) { a0r[b] = 0.0f; a1r[b] = 0.0f; }
                #pragma unroll
                for (int r = 0; r < 4; r++) {
                    int rg = r0g + r;
                    int h = rg / 33;
                    int c = rg - 33 * h;
                    float bias = s_b2[rg];
                    int sl = h - h0;
                    #pragma unroll
                    for (int p = 0; p < 4; p++) {
                        float2 f = u2f(acc[r][p]);
                        float t0 = tanh_fast(f.x + bias);
                        float t1 = tanh_fast(f.y + bias);
                        float g0 = t0 * s_dx[(2 * p) * 34 + c];
                        float g1 = t1 * s_dx[(2 * p + 1) * 34 + c];
                        if (sl == 0) { a0r[2 * p] += g0; a0r[2 * p + 1] += g1; }
                        else         { a1r[2 * p] += g0; a1r[2 * p + 1] += g1; }
                    }
                }
                #pragma unroll
                for (int b = 0; b < 8; b++) {
                    atomicAdd(&s_k[sub][b * 32 + h0], a0r[b]);
                    atomicAdd(&s_k[sub][b * 32 + h0 + 1], a1r[b]);
                }
                // leftover epilogue (one lane per row): rows 1024.. have h=31
                if ((lane & 7) == 0) {
                    int c = lr - 1023;
                    float bias = s_b2[lr];
                    #pragma unroll
                    for (int p = 0; p < 4; p++) {
                        float2 f = u2f(lacc[p]);
                        float t0 = tanh_fast(f.x + bias);
                        float t1 = tanh_fast(f.y + bias);
                        atomicAdd(&s_k[sub][(2 * p) * 32 + 31],     t0 * s_dx[(2 * p) * 34 + c]);
                        atomicAdd(&s_k[sub][(2 * p + 1) * 32 + 31], t1 * s_dx[(2 * p + 1) * 34 + c]);
                    }
                }
            }
            __syncthreads();
        }
    }

    // ---- final z write ----
    {
        float c1 = s_k[0][tid], c2 = s_k[1][tid], c3 = s_k[2][tid], c4 = s_k[3][tid];
        float zf = s_z[tid] + (c1 + 2.0f * (c2 + c3) + c4) * (1.0f / 6.0f);
        int b = tid >> 5, h = tid & 31;
        g_z[(b0 + b) * HH + h] = zf;
    }
}

// ---------------- fused te + fv ----------------------------------------------
__global__ void k_tefv(const float* __restrict__ rec_w, const float* __restrict__ rec_b,
                       const float* __restrict__ fcv_w, const float* __restrict__ fcv_b,
                       const int* __restrict__ last_nodes) {
    int b = blockIdx.x, t = threadIdx.x;
    __shared__ float zs[HH];
    __shared__ float fs[DD];
    if (t < HH) zs[t] = g_z[b * HH + t];
    if (t >= 128) fs[t - 128] = g_featn[(size_t)last_nodes[b] * DD + (t - 128)];
    __syncthreads();
    if (t < 128) {
        float acc = rec_b[t];
        #pragma unroll
        for (int h = 0; h < HH; h++) acc += zs[h] * rec_w[t * HH + h];
        g_te[b * DD + t] = acc;
    } else {
        int d = t - 128;
        const float4* w4 = (const float4*)(fcv_w + d * DD);
        const float4* f4 = (const float4*)fs;
        float acc = fcv_b[d];
        #pragma unroll 8
        for (int k = 0; k < 32; k++) acc += dot4(f4[k], w4[k]);
        g_fv[b * DD + d] = acc;
    }
}

// ---------------- e[n] = sigmoid(featn@fcu.T + fv[seg]) . fce ----------------
__global__ void k_e(const float* __restrict__ fcu_w, const float* __restrict__ fce_w,
                    const int* __restrict__ seg_ids) {
    int n0 = blockIdx.x * 16;
    int d = threadIdx.x;
    __shared__ float fs[16][128];
    __shared__ float es[16];
    for (int i = d; i < 16 * 128; i += 128) ((float*)fs)[i] = g_featn[(size_t)n0 * DD + i];
    if (d < 16) es[d] = 0.0f;
    __syncthreads();
    float acc[16];
    #pragma unroll
    for (int n = 0; n < 16; n++) acc[n] = 0.0f;
    const float4* w4 = (const float4*)(fcu_w + d * DD);
    for (int k4 = 0; k4 < 32; k4++) {
        float4 wv = w4[k4];
        #pragma unroll
        for (int n = 0; n < 16; n++) {
            float4 a = *(const float4*)(&fs[n][k4 * 4]);
            acc[n] += dot4(a, wv);
        }
    }
    float fcw = fce_w[d];
    #pragma unroll
    for (int n = 0; n < 16; n++) {
        int seg = seg_ids[n0 + n];
        float s = fcw / (1.0f + expf(-(acc[n] + g_fv[seg * DD + d])));
        #pragma unroll
        for (int o = 16; o; o >>= 1) s += __shfl_xor_sync(0xffffffffu, s, o);
        if ((d & 31) == 0) atomicAdd(&es[n], s);
    }
    __syncthreads();
    if (d < 16) g_e[n0 + d] = es[d];
}

// ---------------- segment softmax + sr (writes transposed srT) ---------------
__global__ void k_seg(const float* __restrict__ fcsr_w, const int* __restrict__ last_nodes) {
    int b = blockIdx.x, d = threadIdx.x;
    __shared__ float al[LL];
    __shared__ float srl[DD], srg[DD];
    __shared__ float red[4];
    if (d == 0) {
        float m = -1e30f;
        for (int n = 0; n < LL; n++) m = fmaxf(m, g_e[b * LL + n]);
        float s = 0.0f;
        for (int n = 0; n < LL; n++) { float ee = expf(g_e[b * LL + n] - m); al[n] = ee; s += ee; }
        float inv = 1.0f / s;
        for (int n = 0; n < LL; n++) al[n] *= inv;
    }
    __syncthreads();
    float sg = 0.0f;
    for (int n = 0; n < LL; n++) sg += al[n] * g_featn[(size_t)(b * LL + n) * DD + d];
    float sl = g_featn[(size_t)last_nodes[b] * DD + d];
    srl[d] = sl; srg[d] = sg;
    __syncthreads();
    float acc = g_te[b * DD + d];
    const float4* w4 = (const float4*)(fcsr_w + d * 2 * DD);
    const float4* l4 = (const float4*)srl;
    const float4* g4 = (const float4*)srg;
    #pragma unroll 8
    for (int k = 0; k < 32; k++) acc += dot4(l4[k], w4[k]);
    #pragma unroll 8
    for (int k = 0; k < 32; k++) acc += dot4(g4[k], w4[32 + k]);
    float ss = acc * acc;
    #pragma unroll
    for (int o = 16; o; o >>= 1) ss += __shfl_xor_sync(0xffffffffu, ss, o);
    if ((d & 31) == 0) red[d >> 5] = ss;
    __syncthreads();
    float tot = red[0] + red[1] + red[2] + red[3];
    float inv = 1.0f / (sqrtf(tot) + 1e-12f);
    g_srT[d * BB + b] = acc * inv;
}

// ---------------- logits GEMM (f32x2, srT, max-based softmax) -----------------
// grid (4 b-tiles, 782 v-tiles), 256 threads, tile 128b x 128v
#define LOG_SMEM_FLOATS (128*128 + 128*128 + 128 + 128)
__global__ void __launch_bounds__(256) k_logits(float* __restrict__ out) {
    extern __shared__ float sm[];
    float* sA = sm;                  // [k=128][b=128]
    float* sB = sA + 128 * 128;      // [v=128][k=128]
    float* sM = sB + 128 * 128;      // 128
    float* sS = sM + 128;            // 128
    int bt = blockIdx.x, vt = blockIdx.y;
    int b0c = bt * 128, v0c = vt * 128;
    int tid = threadIdx.x;
    bool full = (v0c + 128 <= VV);

    #pragma unroll
    for (int j = 0; j < 16; j++) {
        int idx4 = tid + j * 256;
        int k = idx4 >> 5, q = idx4 & 31;
        ((float4*)(sA + k * 128))[q] = ((const float4*)(g_srT + (size_t)k * BB + b0c))[q];
    }
    #pragma unroll
    for (int j = 0; j < 16; j++) {
        int idx4 = tid + j * 256;
        int v = idx4 >> 5, k4 = idx4 & 31;
        int vg = v0c + v;
        float4 val = make_float4(0.f, 0.f, 0.f, 0.f);
        if (vg < VV) val = ((const float4*)(g_embn + (size_t)vg * DD))[k4];
        ((float4*)(sB + v * 128))[k4] = val;
    }
    if (tid < 128) { sM[tid] = -1e30f; sS[tid] = 0.0f; }
    __syncthreads();

    int w = tid >> 5, lane = tid & 31;
    int bq = lane & 15, vh = lane >> 4;
    int v0l = w * 16 + vh * 8;

    ull acc[4][8];
    #pragma unroll
    for (int p = 0; p < 4; p++)
        #pragma unroll
        for (int j = 0; j < 8; j++) acc[p][j] = 0ULL;

    #pragma unroll 1
    for (int k4 = 0; k4 < 32; k4++) {
        int k = k4 * 4;
        float4 bv[8];
        #pragma unroll
        for (int j = 0; j < 8; j++) bv[j] = *(const float4*)&sB[(v0l + j) * 128 + k];
        #pragma unroll
        for (int i = 0; i < 4; i++) {
            ull a[4];
            #pragma unroll
            for (int p = 0; p < 4; p++) a[p] = *(const ull*)&sA[(k + i) * 128 + 2 * bq + 32 * p];
            #pragma unroll
            for (int j = 0; j < 8; j++) {
                float c = (i == 0) ? bv[j].x : (i == 1) ? bv[j].y : (i == 2) ? bv[j].z : bv[j].w;
                ull bd = dup2(c);
                #pragma unroll
                for (int p = 0; p < 4; p++) acc[p][j] = ffma2(a[p], bd, acc[p][j]);
            }
        }
    }

    // phase 1: per-b tile max
    #pragma unroll
    for (int p = 0; p < 4; p++) {
        int be = 2 * bq + 32 * p;
        float me = -1e30f, mo = -1e30f;
        #pragma unroll
        for (int j = 0; j < 8; j++) {
            if (full || (v0c + v0l + j < VV)) {
                float2 f = u2f(acc[p][j]);
                me = fmaxf(me, SCALE_F * f.x);
                mo = fmaxf(mo, SCALE_F * f.y);
            }
        }
        atomicMaxFloatShared(&sM[be], me);
        atomicMaxFloatShared(&sM[be + 1], mo);
    }
    __syncthreads();

    // phase 2: exp-sums + store logits
    #pragma unroll
    for (int p = 0; p < 4; p++) {
        int be = 2 * bq + 32 * p, bo = be + 1;
        float m0 = sM[be], m1 = sM[bo];
        float s0 = 0.0f, s1 = 0.0f;
        float r0a[8], r1a[8];
        #pragma unroll
        for (int j = 0; j < 8; j++) {
            float2 f = u2f(acc[p][j]);
            float x = SCALE_F * f.x, y = SCALE_F * f.y;
            r0a[j] = x; r1a[j] = y;
            if (full || (v0c + v0l + j < VV)) {
                s0 += __expf(x - m0);
                s1 += __expf(y - m1);
            }
        }
        size_t base0 = (size_t)(b0c + be) * VV + v0c + v0l;
        size_t base1 = (size_t)(b0c + bo) * VV + v0c + v0l;
        if (full) {
            ((float4*)(out + base0))[0] = make_float4(r0a[0], r0a[1], r0a[2], r0a[3]);
            ((float4*)(out + base0))[1] = make_float4(r0a[4], r0a[5], r0a[6], r0a[7]);
            ((float4*)(out + base1))[0] = make_float4(r1a[0], r1a[1], r1a[2], r1a[3]);
            ((float4*)(out + base1))[1] = make_float4(r1a[4], r1a[5], r1a[6], r1a[7]);
        } else {
            #pragma unroll
            for (int j = 0; j < 8; j++) {
                if (v0c + v0l + j < VV) {
                    out[base0 + j] = r0a[j];
                    out[base1 + j] = r1a[j];
                }
            }
        }
        atomicAdd(&sS[be], s0);
        atomicAdd(&sS[bo], s1);
    }
    __syncthreads();
    if (tid < 128) {
        g_pmax[(size_t)(b0c + tid) * VTILES + vt] = sM[tid];
        g_psum[(size_t)(b0c + tid) * VTILES + vt] = sS[tid];
    }
}

// ---------------- lse reduce (max-based) --------------------------------------
__global__ void k_lse() {
    int b = blockIdx.x, tid = threadIdx.x;
    __shared__ float red[256];
    float m = -1e30f;
    for (int t = tid; t < VTILES; t += 256) m = fmaxf(m, g_pmax[(size_t)b * VTILES + t]);
    red[tid] = m;
    __syncthreads();
    for (int o = 128; o; o >>= 1) { if (tid < o) red[tid] = fmaxf(red[tid], red[tid + o]); __syncthreads(); }
    float M = red[0];
    __syncthreads();
    float s = 0.0f;
    for (int t = tid; t < VTILES; t += 256)
        s += g_psum[(size_t)b * VTILES + t] * expf(g_pmax[(size_t)b * VTILES + t] - M);
    red[tid] = s;
    __syncthreads();
    for (int o = 128; o; o >>= 1) { if (tid < o) red[tid] += red[tid + o]; __syncthreads(); }
    if (tid == 0) g_lse[b] = M + logf(red[0]);
}

// ---------------- final fix: out -= lse[b] (2D grid, no div) ------------------
__global__ void k_fix(float* __restrict__ out) {
    int b = blockIdx.y;
    int i4 = blockIdx.x * 256 + threadIdx.x;
    if (i4 >= VV / 4) return;
    float l = g_lse[b];
    float4* o4 = (float4*)(out + (size_t)b * VV);
    float4 v = o4[i4];
    v.x -= l; v.y -= l; v.z -= l; v.w -= l;
    o4[i4] = v;
}

// =============================================================================
extern "C" void kernel_launch(void* const* d_in, const int* in_sizes, int n_in,
                              void* d_out, int out_size) {
    const float* emb      = (const float*)d_in[0];
    const float* fcu_w    = (const float*)d_in[7];
    const float* fcv_w    = (const float*)d_in[8];
    const float* fcv_b    = (const float*)d_in[9];
    const float* fce_w    = (const float*)d_in[10];
    const float* fcsr_w   = (const float*)d_in[11];
    const float* red_w    = (const float*)d_in[12];
    const float* red_b    = (const float*)d_in[13];
    const float* rec_w    = (const float*)d_in[14];
    const float* rec_b    = (const float*)d_in[15];
    const float* cde_w1   = (const float*)d_in[16];
    const float* cde_b1   = (const float*)d_in[17];
    const float* cde_w2   = (const float*)d_in[18];
    const float* cde_b2   = (const float*)d_in[19];
    const float* init_w   = (const float*)d_in[20];
    const float* init_b   = (const float*)d_in[21];
    const float* times    = (const float*)d_in[23];
    const int*   iid      = (const int*)d_in[24];
    const int*   seg_ids  = (const int*)d_in[27];
    const int*   last_nd  = (const int*)d_in[28];
    const int*   eids     = (const int*)d_in[29];
    float* out = (float*)d_out;

    const int log_smem = LOG_SMEM_FLOATS * 4;
    cudaFuncSetAttribute(k_logits, cudaFuncAttributeMaxDynamicSharedMemorySize, log_smem);

    k_misc<<<15060, 256>>>(emb, iid, eids, red_w, red_b, times);    // launch 1
    k_w2t<<<(RR * DD + 255) / 256, 256>>>(cde_w2);                   // launch 2
    k_noop<<<1, 32>>>();                                             // launch 3
    k_scan<<<64, 256>>>(cde_w1, cde_b1, cde_b2, init_w, init_b);     // launch 4 (profiled)
    k_tefv<<<BB, 256>>>(rec_w, rec_b, fcv_w, fcv_b, last_nd);
    k_e<<<NN / 16, 128>>>(fcu_w, fce_w, seg_ids);
    k_seg<<<BB, 128>>>(fcsr_w, last_nd);
    k_logits<<<dim3(4, VTILES), 256, log_smem>>>(out);
    k_lse<<<BB, 256>>>();
    k_fix<<<dim3((VV / 4 + 255) / 256, BB), 256>>>(out);
}